// round 1
// baseline (speedup 1.0000x reference)
#include <cuda_runtime.h>
#include <cuda_bf16.h>

// Factorized ray-marching:
//   x@W1 + b1 = p1 + alpha * u,   p1 = pivot@W1 + b1 (256-vec),  u = r_norm@W1 (per row)
// So the B x 128 x 256 GEMM happens ONCE; the 20 iterations are per-row
// recurrences over 256 hidden units held in registers (8 per lane, warp/row).

#define D_DIM 128
#define H_DIM 256

__device__ float g_p1[H_DIM];

__device__ __forceinline__ float tanh_fast(float x) {
    float y;
    asm("tanh.approx.f32 %0, %1;" : "=f"(y) : "f"(x));
    return y;
}

// p1[j] = b1[j] + sum_d pivot[d] * W1[d][j]   (1 block, 256 threads, coalesced over j)
__global__ void p1_kernel(const float* __restrict__ pivot,
                          const float* __restrict__ W1,
                          const float* __restrict__ b1) {
    int j = threadIdx.x;            // 0..255
    float s = b1[j];
#pragma unroll 8
    for (int d = 0; d < D_DIM; ++d)
        s = fmaf(pivot[d], W1[d * H_DIM + j], s);
    g_p1[j] = s;
}

__global__ __launch_bounds__(256)
void raymarch_kernel(const float* __restrict__ r,
                     const float* __restrict__ s_in,
                     const float* __restrict__ pivot,
                     const float* __restrict__ W1,
                     const float* __restrict__ w2,
                     const float* __restrict__ b2,
                     const int* __restrict__ n_iter_ptr,
                     float* __restrict__ out,
                     int B) {
    const int warp = (int)((blockIdx.x * blockDim.x + threadIdx.x) >> 5);
    const int lane = threadIdx.x & 31;
    if (warp >= B) return;

    const float* rrow = r + (size_t)warp * D_DIM;

    // ---- load r in shuffle-broadcast layout: lane holds r[lane + 32k] ----
    float r0 = rrow[lane];
    float r1 = rrow[lane + 32];
    float r2 = rrow[lane + 64];
    float r3 = rrow[lane + 96];

    float ss = r0 * r0 + r1 * r1 + r2 * r2 + r3 * r3;
#pragma unroll
    for (int o = 16; o; o >>= 1) ss += __shfl_xor_sync(0xffffffffu, ss, o);
    const float inv_norm = rsqrtf(ss);

    // ---- u = r @ W1 (scale by inv_norm afterwards) ----
    // lane owns columns: c0..c0+3 and 128+c0..128+c0+3  (c0 = lane*4) -> coalesced float4 loads
    const int c0 = lane * 4;
    float u[8];
#pragma unroll
    for (int i = 0; i < 8; ++i) u[i] = 0.f;

#pragma unroll
    for (int k = 0; k < 4; ++k) {
        float rk = (k == 0) ? r0 : (k == 1) ? r1 : (k == 2) ? r2 : r3;
#pragma unroll
        for (int l = 0; l < 32; ++l) {
            float rd = __shfl_sync(0xffffffffu, rk, l);
            const float* wrow = W1 + (size_t)(k * 32 + l) * H_DIM;
            float4 wa = *(const float4*)(wrow + c0);
            float4 wb = *(const float4*)(wrow + 128 + c0);
            u[0] = fmaf(rd, wa.x, u[0]);
            u[1] = fmaf(rd, wa.y, u[1]);
            u[2] = fmaf(rd, wa.z, u[2]);
            u[3] = fmaf(rd, wa.w, u[3]);
            u[4] = fmaf(rd, wb.x, u[4]);
            u[5] = fmaf(rd, wb.y, u[5]);
            u[6] = fmaf(rd, wb.z, u[6]);
            u[7] = fmaf(rd, wb.w, u[7]);
        }
    }
#pragma unroll
    for (int i = 0; i < 8; ++i) u[i] *= inv_norm;

    // ---- per-lane p1 and w2 slices ----
    float4 pa = *(const float4*)(g_p1 + c0);
    float4 pb = *(const float4*)(g_p1 + 128 + c0);
    float p1v[8] = {pa.x, pa.y, pa.z, pa.w, pb.x, pb.y, pb.z, pb.w};
    float4 wva = *(const float4*)(w2 + c0);
    float4 wvb = *(const float4*)(w2 + 128 + c0);
    float w2v[8] = {wva.x, wva.y, wva.z, wva.w, wvb.x, wvb.y, wvb.z, wvb.w};

    const float b2v = b2[0];
    const int n = n_iter_ptr ? *n_iter_ptr : 20;

    // ---- 20-step recurrence: alpha += 0.05*(1 + tanh( tanh(p1+alpha*u) @ w2 + b2 )) ----
    float alpha = 0.f;
    for (int it = 0; it < n; ++it) {
        float acc = 0.f;
#pragma unroll
        for (int i = 0; i < 8; ++i) {
            float z = fmaf(alpha, u[i], p1v[i]);
            acc = fmaf(tanh_fast(z), w2v[i], acc);
        }
#pragma unroll
        for (int o = 16; o; o >>= 1) acc += __shfl_xor_sync(0xffffffffu, acc, o);
        alpha += 0.05f * (1.0f + tanh_fast(acc + b2v));
    }

    // ---- output: out = pivot + sigmoid(s)*alpha * r * inv_norm ----
    const float sv = s_in[warp];
    const float sig = 1.0f / (1.0f + __expf(-sv));
    const float fscale = sig * alpha * inv_norm;

    float4 rv = *(const float4*)(rrow + c0);
    float4 pv = *(const float4*)(pivot + c0);
    float4 o;
    o.x = fmaf(fscale, rv.x, pv.x);
    o.y = fmaf(fscale, rv.y, pv.y);
    o.z = fmaf(fscale, rv.z, pv.z);
    o.w = fmaf(fscale, rv.w, pv.w);
    *(float4*)(out + (size_t)warp * D_DIM + c0) = o;
}

extern "C" void kernel_launch(void* const* d_in, const int* in_sizes, int n_in,
                              void* d_out, int out_size) {
    const float* r     = (const float*)d_in[0];   // [B,128]
    const float* s     = (const float*)d_in[1];   // [B,1]
    const float* pivot = (const float*)d_in[2];   // [128]
    const float* W1    = (const float*)d_in[3];   // [128,256]
    const float* b1    = (const float*)d_in[4];   // [256]
    const float* w2    = (const float*)d_in[5];   // [256]
    const float* b2    = (const float*)d_in[6];   // [1]
    const int* n_iter  = (n_in > 7) ? (const int*)d_in[7] : nullptr;
    float* out = (float*)d_out;

    const int B = in_sizes[0] / D_DIM;

    p1_kernel<<<1, H_DIM>>>(pivot, W1, b1);

    const int warps_per_block = 256 / 32;                 // 8 rows per block
    const int blocks = (B + warps_per_block - 1) / warps_per_block;
    raymarch_kernel<<<blocks, 256>>>(r, s, pivot, W1, w2, b2, n_iter, out, B);
}

// round 2
// speedup vs baseline: 1.4388x; 1.4388x over previous
#include <cuda_runtime.h>
#include <cuda_bf16.h>

// Factorized ray-marching (x@W1+b1 = p1 + alpha*u, GEMM once, 20 scalar steps).
// R2: 4 rows per warp (W1 L1 traffic /4) + packed fma.rn.f32x2 (FFMA instrs /2).

#define D_DIM 128
#define H_DIM 256
#define ROWS  4

__device__ float g_p1[H_DIM];

static __device__ __forceinline__ float tanh_fast(float x) {
    float y; asm("tanh.approx.f32 %0, %1;" : "=f"(y) : "f"(x)); return y;
}
static __device__ __forceinline__ unsigned long long pack2(float lo, float hi) {
    unsigned long long r;
    asm("mov.b64 %0, {%1, %2};" : "=l"(r) : "f"(lo), "f"(hi));
    return r;
}
static __device__ __forceinline__ void unpack2(unsigned long long p, float& lo, float& hi) {
    asm("mov.b64 {%0, %1}, %2;" : "=f"(lo), "=f"(hi) : "l"(p));
}
static __device__ __forceinline__ void ffma2(unsigned long long& d,
                                             unsigned long long a,
                                             unsigned long long b) {
    asm("fma.rn.f32x2 %0, %1, %2, %0;" : "+l"(d) : "l"(a), "l"(b));
}

// p1[j] = b1[j] + sum_d pivot[d] * W1[d][j]
__global__ void p1_kernel(const float* __restrict__ pivot,
                          const float* __restrict__ W1,
                          const float* __restrict__ b1) {
    int j = threadIdx.x;
    float s = b1[j];
#pragma unroll 8
    for (int d = 0; d < D_DIM; ++d)
        s = fmaf(pivot[d], W1[d * H_DIM + j], s);
    g_p1[j] = s;
}

__global__ __launch_bounds__(256)
void raymarch_kernel(const float* __restrict__ r,
                     const float* __restrict__ s_in,
                     const float* __restrict__ pivot,
                     const float* __restrict__ W1,
                     const float* __restrict__ w2,
                     const float* __restrict__ b2,
                     const int* __restrict__ n_iter_ptr,
                     float* __restrict__ out,
                     int B) {
    const int lane = threadIdx.x & 31;
    const int warp = blockIdx.x * (blockDim.x >> 5) + (threadIdx.x >> 5);
    const int row0 = warp * ROWS;
    if (row0 >= B) return;

    // ---- load r for 4 rows in shuffle layout: lane holds r[m][lane + 32k] ----
    float rreg[ROWS][4];
    float inv_norm[ROWS];
#pragma unroll
    for (int m = 0; m < ROWS; ++m) {
        const bool act = (row0 + m) < B;
        const float* rr = r + (size_t)(row0 + m) * D_DIM;
        float ss = 0.f;
#pragma unroll
        for (int k = 0; k < 4; ++k) {
            float v = act ? rr[lane + 32 * k] : 0.f;
            rreg[m][k] = v;
            ss = fmaf(v, v, ss);
        }
#pragma unroll
        for (int o = 16; o; o >>= 1) ss += __shfl_xor_sync(0xffffffffu, ss, o);
        inv_norm[m] = rsqrtf(ss);
    }

    // ---- u[m] = r[m] @ W1, columns c0..c0+3 and 128+c0..128+c0+3 per lane ----
    const int c0 = lane * 4;
    unsigned long long acc[ROWS][4];
#pragma unroll
    for (int m = 0; m < ROWS; ++m)
#pragma unroll
        for (int p = 0; p < 4; ++p) acc[m][p] = pack2(0.f, 0.f);

#pragma unroll
    for (int k = 0; k < 4; ++k) {
#pragma unroll 4
        for (int l = 0; l < 32; ++l) {
            const float* wrow = W1 + (size_t)(k * 32 + l) * H_DIM;
            float4 wa = *(const float4*)(wrow + c0);
            float4 wb = *(const float4*)(wrow + 128 + c0);
            unsigned long long w01 = pack2(wa.x, wa.y);
            unsigned long long w23 = pack2(wa.z, wa.w);
            unsigned long long w45 = pack2(wb.x, wb.y);
            unsigned long long w67 = pack2(wb.z, wb.w);
#pragma unroll
            for (int m = 0; m < ROWS; ++m) {
                float rd = __shfl_sync(0xffffffffu, rreg[m][k], l);
                unsigned long long rdd = pack2(rd, rd);
                ffma2(acc[m][0], rdd, w01);
                ffma2(acc[m][1], rdd, w23);
                ffma2(acc[m][2], rdd, w45);
                ffma2(acc[m][3], rdd, w67);
            }
        }
    }

    // ---- unpack u, apply inv_norm ----
    float u[ROWS][8];
#pragma unroll
    for (int m = 0; m < ROWS; ++m) {
#pragma unroll
        for (int p = 0; p < 4; ++p)
            unpack2(acc[m][p], u[m][2 * p], u[m][2 * p + 1]);
#pragma unroll
        for (int i = 0; i < 8; ++i) u[m][i] *= inv_norm[m];
    }

    // ---- per-lane p1 / w2 slices ----
    float4 pa = *(const float4*)(g_p1 + c0);
    float4 pb = *(const float4*)(g_p1 + 128 + c0);
    float p1v[8] = {pa.x, pa.y, pa.z, pa.w, pb.x, pb.y, pb.z, pb.w};
    float4 wva = *(const float4*)(w2 + c0);
    float4 wvb = *(const float4*)(w2 + 128 + c0);
    float w2v[8] = {wva.x, wva.y, wva.z, wva.w, wvb.x, wvb.y, wvb.z, wvb.w};

    const float b2v = b2[0];
    const int n = n_iter_ptr ? *n_iter_ptr : 20;

    // ---- 20-step recurrence, 4 rows interleaved for ILP ----
    float alpha[ROWS] = {0.f, 0.f, 0.f, 0.f};
    for (int it = 0; it < n; ++it) {
        float accs[ROWS] = {0.f, 0.f, 0.f, 0.f};
#pragma unroll
        for (int i = 0; i < 8; ++i) {
#pragma unroll
            for (int m = 0; m < ROWS; ++m) {
                float z = fmaf(alpha[m], u[m][i], p1v[i]);
                accs[m] = fmaf(tanh_fast(z), w2v[i], accs[m]);
            }
        }
#pragma unroll
        for (int o = 16; o; o >>= 1) {
#pragma unroll
            for (int m = 0; m < ROWS; ++m)
                accs[m] += __shfl_xor_sync(0xffffffffu, accs[m], o);
        }
#pragma unroll
        for (int m = 0; m < ROWS; ++m)
            alpha[m] += 0.05f * (1.0f + tanh_fast(accs[m] + b2v));
    }

    // ---- output: out = pivot + sigmoid(s)*alpha*inv_norm * r ----
    float4 pv = *(const float4*)(pivot + c0);
#pragma unroll
    for (int m = 0; m < ROWS; ++m) {
        if (row0 + m >= B) break;
        const float sv = s_in[row0 + m];
        const float sig = 1.0f / (1.0f + __expf(-sv));
        const float fscale = sig * alpha[m] * inv_norm[m];

        float4 rv = *(const float4*)(r + (size_t)(row0 + m) * D_DIM + c0);
        float4 o;
        o.x = fmaf(fscale, rv.x, pv.x);
        o.y = fmaf(fscale, rv.y, pv.y);
        o.z = fmaf(fscale, rv.z, pv.z);
        o.w = fmaf(fscale, rv.w, pv.w);
        *(float4*)(out + (size_t)(row0 + m) * D_DIM + c0) = o;
    }
}

extern "C" void kernel_launch(void* const* d_in, const int* in_sizes, int n_in,
                              void* d_out, int out_size) {
    const float* r     = (const float*)d_in[0];   // [B,128]
    const float* s     = (const float*)d_in[1];   // [B,1]
    const float* pivot = (const float*)d_in[2];   // [128]
    const float* W1    = (const float*)d_in[3];   // [128,256]
    const float* b1    = (const float*)d_in[4];   // [256]
    const float* w2    = (const float*)d_in[5];   // [256]
    const float* b2    = (const float*)d_in[6];   // [1]
    const int* n_iter  = (n_in > 7) ? (const int*)d_in[7] : nullptr;
    float* out = (float*)d_out;

    const int B = in_sizes[0] / D_DIM;

    p1_kernel<<<1, H_DIM>>>(pivot, W1, b1);

    const int rows_per_block = (256 / 32) * ROWS;  // 32 rows/block
    const int blocks = (B + rows_per_block - 1) / rows_per_block;
    raymarch_kernel<<<blocks, 256>>>(r, s, pivot, W1, w2, b2, n_iter, out, B);
}

// round 3
// speedup vs baseline: 1.4890x; 1.0348x over previous
#include <cuda_runtime.h>
#include <cuda_fp16.h>
#include <cuda_bf16.h>

// Factorized ray-marching: x@W1+b1 = p1 + alpha*u. GEMM once (f32, FFMA2),
// 20-step recurrence in f16x2 (tanh.approx.f16x2) with 8-lane-group layout:
// warp = 4 rows, each 8-lane group owns one row (32 H-cols/lane), so the
// per-iteration reduction is 3 shfl_xor for the whole warp.

#define D_DIM 128
#define H_DIM 256
#define ROWS  4

__device__ float   g_p1[H_DIM];
__device__ __half2 g_p1h2[H_DIM / 2];
__device__ __half2 g_w2h2[H_DIM / 2];

static __device__ __forceinline__ float tanh_fast(float x) {
    float y; asm("tanh.approx.f32 %0, %1;" : "=f"(y) : "f"(x)); return y;
}
static __device__ __forceinline__ __half2 tanh2_fast(__half2 x) {
    __half2 y;
    asm("tanh.approx.f16x2 %0, %1;"
        : "=r"(*(unsigned*)&y) : "r"(*(unsigned*)&x));
    return y;
}
static __device__ __forceinline__ unsigned long long pack2(float lo, float hi) {
    unsigned long long r;
    asm("mov.b64 %0, {%1, %2};" : "=l"(r) : "f"(lo), "f"(hi));
    return r;
}
static __device__ __forceinline__ void unpack2(unsigned long long p, float& lo, float& hi) {
    asm("mov.b64 {%0, %1}, %2;" : "=f"(lo), "=f"(hi) : "l"(p));
}
static __device__ __forceinline__ void ffma2(unsigned long long& d,
                                             unsigned long long a,
                                             unsigned long long b) {
    asm("fma.rn.f32x2 %0, %1, %2, %0;" : "+l"(d) : "l"(a), "l"(b));
}

// prep: p1 = pivot@W1 + b1 (f32), plus half2 copies of p1 and w2.
__global__ void prep_kernel(const float* __restrict__ pivot,
                            const float* __restrict__ W1,
                            const float* __restrict__ b1,
                            const float* __restrict__ w2) {
    __shared__ float sp1[H_DIM];
    int j = threadIdx.x;
    float s = b1[j];
#pragma unroll 8
    for (int d = 0; d < D_DIM; ++d)
        s = fmaf(pivot[d], W1[d * H_DIM + j], s);
    g_p1[j] = s;
    sp1[j] = s;
    __syncthreads();
    if (j < H_DIM / 2) {
        g_p1h2[j] = __floats2half2_rn(sp1[2 * j], sp1[2 * j + 1]);
        g_w2h2[j] = __floats2half2_rn(w2[2 * j], w2[2 * j + 1]);
    }
}

__global__ __launch_bounds__(256)
void raymarch_kernel(const float* __restrict__ r,
                     const float* __restrict__ s_in,
                     const float* __restrict__ pivot,
                     const float* __restrict__ W1,
                     const float* __restrict__ w2,
                     const float* __restrict__ b2,
                     const int* __restrict__ n_iter_ptr,
                     float* __restrict__ out,
                     int B) {
    __shared__ __half u_sh[8][ROWS * H_DIM];   // 16 KB: per-warp u in half

    const int lane = threadIdx.x & 31;
    const int wib  = threadIdx.x >> 5;
    const int warp = blockIdx.x * (blockDim.x >> 5) + wib;
    const int row0 = warp * ROWS;
    if (row0 >= B) return;

    // ============ Phase A: u[m] = r[m] @ W1 (f32, FFMA2), 4 rows/warp ============
    float rreg[ROWS][4];
    float inv_norm[ROWS];
#pragma unroll
    for (int m = 0; m < ROWS; ++m) {
        const bool act = (row0 + m) < B;
        const float* rr = r + (size_t)(row0 + m) * D_DIM;
        float ss = 0.f;
#pragma unroll
        for (int k = 0; k < 4; ++k) {
            float v = act ? rr[lane + 32 * k] : 0.f;
            rreg[m][k] = v;
            ss = fmaf(v, v, ss);
        }
#pragma unroll
        for (int o = 16; o; o >>= 1) ss += __shfl_xor_sync(0xffffffffu, ss, o);
        inv_norm[m] = act ? rsqrtf(ss) : 0.f;
    }

    const int c0 = lane * 4;
    unsigned long long acc[ROWS][4];
#pragma unroll
    for (int m = 0; m < ROWS; ++m)
#pragma unroll
        for (int p = 0; p < 4; ++p) acc[m][p] = pack2(0.f, 0.f);

#pragma unroll
    for (int k = 0; k < 4; ++k) {
#pragma unroll 4
        for (int l = 0; l < 32; ++l) {
            const float* wrow = W1 + (size_t)(k * 32 + l) * H_DIM;
            float4 wa = *(const float4*)(wrow + c0);
            float4 wb = *(const float4*)(wrow + 128 + c0);
            unsigned long long w01 = pack2(wa.x, wa.y);
            unsigned long long w23 = pack2(wa.z, wa.w);
            unsigned long long w45 = pack2(wb.x, wb.y);
            unsigned long long w67 = pack2(wb.z, wb.w);
#pragma unroll
            for (int m = 0; m < ROWS; ++m) {
                float rd = __shfl_sync(0xffffffffu, rreg[m][k], l);
                unsigned long long rdd = pack2(rd, rd);
                ffma2(acc[m][0], rdd, w01);
                ffma2(acc[m][1], rdd, w23);
                ffma2(acc[m][2], rdd, w45);
                ffma2(acc[m][3], rdd, w67);
            }
        }
    }

    // scale by inv_norm, convert to half, stage to smem (cols c0..c0+3, 128+c0..+3)
    __half* us = u_sh[wib];
#pragma unroll
    for (int m = 0; m < ROWS; ++m) {
        float ulo[8];
#pragma unroll
        for (int p = 0; p < 4; ++p) unpack2(acc[m][p], ulo[2 * p], ulo[2 * p + 1]);
#pragma unroll
        for (int i = 0; i < 8; ++i) ulo[i] *= inv_norm[m];
        __half2* d0 = (__half2*)(us + m * H_DIM + c0);
        d0[0] = __floats2half2_rn(ulo[0], ulo[1]);
        d0[1] = __floats2half2_rn(ulo[2], ulo[3]);
        __half2* d1 = (__half2*)(us + m * H_DIM + 128 + c0);
        d1[0] = __floats2half2_rn(ulo[4], ulo[5]);
        d1[1] = __floats2half2_rn(ulo[6], ulo[7]);
    }
    __syncwarp();

    // ============ Phase B: 8-lane group g owns row g; lane owns 32 H-cols ============
    const int g = lane >> 3;        // row within warp
    const int l = lane & 7;         // lane within group

    __half2 u2[16], p12[16], w22[16];
    {
        const __half2* urow = (const __half2*)(us + g * H_DIM) + l * 16;
#pragma unroll
        for (int q = 0; q < 16; ++q) u2[q] = urow[q];
#pragma unroll
        for (int q = 0; q < 16; ++q) p12[q] = g_p1h2[l * 16 + q];
#pragma unroll
        for (int q = 0; q < 16; ++q) w22[q] = g_w2h2[l * 16 + q];
    }

    const float b2v = b2[0];
    const int n = n_iter_ptr ? *n_iter_ptr : 20;

    float alpha = 0.f;
    for (int it = 0; it < n; ++it) {
        const __half2 a2 = __float2half2_rn(alpha);
        __half2 acc2a = __floats2half2_rn(0.f, 0.f);
        __half2 acc2b = __floats2half2_rn(0.f, 0.f);
#pragma unroll
        for (int q = 0; q < 16; q += 2) {
            __half2 za = __hfma2(a2, u2[q], p12[q]);
            __half2 zb = __hfma2(a2, u2[q + 1], p12[q + 1]);
            acc2a = __hfma2(tanh2_fast(za), w22[q], acc2a);
            acc2b = __hfma2(tanh2_fast(zb), w22[q + 1], acc2b);
        }
        __half2 acc2 = __hadd2(acc2a, acc2b);
        float accf = __low2float(acc2) + __high2float(acc2);
        accf += __shfl_xor_sync(0xffffffffu, accf, 1);
        accf += __shfl_xor_sync(0xffffffffu, accf, 2);
        accf += __shfl_xor_sync(0xffffffffu, accf, 4);
        alpha += 0.05f * (1.0f + tanh_fast(accf + b2v));
    }

    // ============ Output: group g writes row row0+g; lane owns dims 16l..16l+15 ============
    const int row = row0 + g;
    if (row < B) {
        const float sv = s_in[row];
        const float sig = 1.0f / (1.0f + __expf(-sv));
        const float fscale = sig * alpha * inv_norm[g];

        const float4* rv4 = (const float4*)(r + (size_t)row * D_DIM) + l * 4;
        const float4* pv4 = (const float4*)pivot + l * 4;
        float4* ov4 = (float4*)(out + (size_t)row * D_DIM) + l * 4;
#pragma unroll
        for (int j = 0; j < 4; ++j) {
            float4 rv = rv4[j];
            float4 pv = pv4[j];
            float4 o;
            o.x = fmaf(fscale, rv.x, pv.x);
            o.y = fmaf(fscale, rv.y, pv.y);
            o.z = fmaf(fscale, rv.z, pv.z);
            o.w = fmaf(fscale, rv.w, pv.w);
            ov4[j] = o;
        }
    }
}

extern "C" void kernel_launch(void* const* d_in, const int* in_sizes, int n_in,
                              void* d_out, int out_size) {
    const float* r     = (const float*)d_in[0];   // [B,128]
    const float* s     = (const float*)d_in[1];   // [B,1]
    const float* pivot = (const float*)d_in[2];   // [128]
    const float* W1    = (const float*)d_in[3];   // [128,256]
    const float* b1    = (const float*)d_in[4];   // [256]
    const float* w2    = (const float*)d_in[5];   // [256]
    const float* b2    = (const float*)d_in[6];   // [1]
    const int* n_iter  = (n_in > 7) ? (const int*)d_in[7] : nullptr;
    float* out = (float*)d_out;

    const int B = in_sizes[0] / D_DIM;

    prep_kernel<<<1, H_DIM>>>(pivot, W1, b1, w2);

    const int rows_per_block = (256 / 32) * ROWS;  // 32 rows/block
    const int blocks = (B + rows_per_block - 1) / rows_per_block;
    raymarch_kernel<<<blocks, 256>>>(r, s, pivot, W1, w2, b2, n_iter, out, B);
}

// round 4
// speedup vs baseline: 1.8598x; 1.2490x over previous
#include <cuda_runtime.h>
#include <cuda_fp16.h>
#include <cuda_bf16.h>

// Factorized ray-marching: x@W1+b1 = p1 + alpha*u.
// R4: W1 converted once to f16 (one LDG.128 per warp per K-row -> L1 traffic
// halved), GEMM in HFMA2 with split accumulators, r_norm folded in before
// broadcast. Iteration phase stays f16x2 with 8-lane-group layout.

#define D_DIM 128
#define H_DIM 256
#define ROWS  4

__device__ float   g_p1[H_DIM];
__device__ __half2 g_p1h2[H_DIM / 2];
__device__ __half2 g_w2h2[H_DIM / 2];
__device__ __half  g_W1h[D_DIM * H_DIM];

static __device__ __forceinline__ float tanh_fast(float x) {
    float y; asm("tanh.approx.f32 %0, %1;" : "=f"(y) : "f"(x)); return y;
}
static __device__ __forceinline__ __half2 tanh2_fast(__half2 x) {
    __half2 y;
    asm("tanh.approx.f16x2 %0, %1;"
        : "=r"(*(unsigned*)&y) : "r"(*(unsigned*)&x));
    return y;
}

// prep: p1 = pivot@W1 + b1 (f32 + half2 copy), w2 half2 copy, W1 -> f16.
__global__ void prep_kernel(const float* __restrict__ pivot,
                            const float* __restrict__ W1,
                            const float* __restrict__ b1,
                            const float* __restrict__ w2) {
    __shared__ float sp1[H_DIM];
    const int j = threadIdx.x;          // 0..255
    if (blockIdx.x == 0) {
        float s = b1[j];
#pragma unroll 8
        for (int d = 0; d < D_DIM; ++d)
            s = fmaf(pivot[d], W1[d * H_DIM + j], s);
        g_p1[j] = s;
        sp1[j] = s;
        __syncthreads();
        if (j < H_DIM / 2) {
            g_p1h2[j] = __floats2half2_rn(sp1[2 * j], sp1[2 * j + 1]);
            g_w2h2[j] = __floats2half2_rn(w2[2 * j], w2[2 * j + 1]);
        }
    }
    // W1 -> f16 (all blocks share the work)
    const int total = D_DIM * H_DIM;
    for (int i = blockIdx.x * blockDim.x + j; i < total; i += gridDim.x * blockDim.x)
        g_W1h[i] = __float2half_rn(W1[i]);
}

__global__ __launch_bounds__(256)
void raymarch_kernel(const float* __restrict__ r,
                     const float* __restrict__ s_in,
                     const float* __restrict__ pivot,
                     const float* __restrict__ w2,
                     const float* __restrict__ b2,
                     const int* __restrict__ n_iter_ptr,
                     float* __restrict__ out,
                     int B) {
    __shared__ __half u_sh[8][ROWS * H_DIM];   // 16 KB: per-warp u in half

    const int lane = threadIdx.x & 31;
    const int wib  = threadIdx.x >> 5;
    const int warp = blockIdx.x * (blockDim.x >> 5) + wib;
    const int row0 = warp * ROWS;
    if (row0 >= B) return;

    // ===== Phase A: u[m] = r_norm[m] @ W1 (f16 HFMA2), 4 rows/warp =====
    // lane holds r[m][lane + 32k]; normalized value duplicated into a half2
    // so a single shfl broadcasts an HFMA2-ready operand.
    __half2 rh2[ROWS][4];
    float inv_norm[ROWS];
#pragma unroll
    for (int m = 0; m < ROWS; ++m) {
        const bool act = (row0 + m) < B;
        const float* rr = r + (size_t)(row0 + m) * D_DIM;
        float v[4];
        float ss = 0.f;
#pragma unroll
        for (int k = 0; k < 4; ++k) {
            v[k] = act ? rr[lane + 32 * k] : 0.f;
            ss = fmaf(v[k], v[k], ss);
        }
#pragma unroll
        for (int o = 16; o; o >>= 1) ss += __shfl_xor_sync(0xffffffffu, ss, o);
        inv_norm[m] = act ? rsqrtf(ss) : 0.f;
#pragma unroll
        for (int k = 0; k < 4; ++k)
            rh2[m][k] = __float2half2_rn(v[k] * inv_norm[m]);
    }

    // lane owns 8 contiguous columns: 8*lane .. 8*lane+7  (4 half2 accums)
    // split accumulators: k<2 -> accA, k>=2 -> accB (shorter f16 chains)
    __half2 accA[ROWS][4], accB[ROWS][4];
    const __half2 h2z = __floats2half2_rn(0.f, 0.f);
#pragma unroll
    for (int m = 0; m < ROWS; ++m)
#pragma unroll
        for (int p = 0; p < 4; ++p) { accA[m][p] = h2z; accB[m][p] = h2z; }

#pragma unroll
    for (int k = 0; k < 4; ++k) {
#pragma unroll 4
        for (int l = 0; l < 32; ++l) {
            const int d = k * 32 + l;
            const uint4 wv = *(const uint4*)(g_W1h + (size_t)d * H_DIM + lane * 8);
            const __half2 w01 = *(const __half2*)&wv.x;
            const __half2 w23 = *(const __half2*)&wv.y;
            const __half2 w45 = *(const __half2*)&wv.z;
            const __half2 w67 = *(const __half2*)&wv.w;
#pragma unroll
            for (int m = 0; m < ROWS; ++m) {
                unsigned rb = __shfl_sync(0xffffffffu,
                                          *(const unsigned*)&rh2[m][k], l);
                const __half2 rd2 = *(const __half2*)&rb;
                __half2* a = (k < 2) ? accA[m] : accB[m];
                a[0] = __hfma2(rd2, w01, a[0]);
                a[1] = __hfma2(rd2, w23, a[1]);
                a[2] = __hfma2(rd2, w45, a[2]);
                a[3] = __hfma2(rd2, w67, a[3]);
            }
        }
    }

    // combine splits, stage u to smem (lane's 8 cols are contiguous)
    __half* us = u_sh[wib];
#pragma unroll
    for (int m = 0; m < ROWS; ++m) {
        __half2* dst = (__half2*)(us + m * H_DIM + lane * 8);
#pragma unroll
        for (int p = 0; p < 4; ++p)
            dst[p] = __hadd2(accA[m][p], accB[m][p]);
    }
    __syncwarp();

    // ===== Phase B: 8-lane group g owns row g; lane owns 32 H-cols =====
    const int g = lane >> 3;
    const int l = lane & 7;

    __half2 u2[16], p12[16], w22[16];
    {
        const __half2* urow = (const __half2*)(us + g * H_DIM) + l * 16;
#pragma unroll
        for (int q = 0; q < 16; ++q) u2[q] = urow[q];
#pragma unroll
        for (int q = 0; q < 16; ++q) p12[q] = g_p1h2[l * 16 + q];
#pragma unroll
        for (int q = 0; q < 16; ++q) w22[q] = g_w2h2[l * 16 + q];
    }

    const float b2v = b2[0];
    const int n = n_iter_ptr ? *n_iter_ptr : 20;

    float alpha = 0.f;
    for (int it = 0; it < n; ++it) {
        const __half2 a2 = __float2half2_rn(alpha);
        __half2 acc2a = h2z, acc2b = h2z;
#pragma unroll
        for (int q = 0; q < 16; q += 2) {
            __half2 za = __hfma2(a2, u2[q], p12[q]);
            __half2 zb = __hfma2(a2, u2[q + 1], p12[q + 1]);
            acc2a = __hfma2(tanh2_fast(za), w22[q], acc2a);
            acc2b = __hfma2(tanh2_fast(zb), w22[q + 1], acc2b);
        }
        __half2 acc2 = __hadd2(acc2a, acc2b);
        float accf = __low2float(acc2) + __high2float(acc2);
        accf += __shfl_xor_sync(0xffffffffu, accf, 1);
        accf += __shfl_xor_sync(0xffffffffu, accf, 2);
        accf += __shfl_xor_sync(0xffffffffu, accf, 4);
        alpha += 0.05f * (1.0f + tanh_fast(accf + b2v));
    }

    // ===== Output: group g writes row row0+g; lane owns dims 16l..16l+15 =====
    const int row = row0 + g;
    if (row < B) {
        const float sv = s_in[row];
        const float sig = 1.0f / (1.0f + __expf(-sv));
        const float fscale = sig * alpha * inv_norm[g];

        const float4* rv4 = (const float4*)(r + (size_t)row * D_DIM) + l * 4;
        const float4* pv4 = (const float4*)pivot + l * 4;
        float4* ov4 = (float4*)(out + (size_t)row * D_DIM) + l * 4;
#pragma unroll
        for (int j = 0; j < 4; ++j) {
            float4 rv = rv4[j];
            float4 pv = pv4[j];
            float4 o;
            o.x = fmaf(fscale, rv.x, pv.x);
            o.y = fmaf(fscale, rv.y, pv.y);
            o.z = fmaf(fscale, rv.z, pv.z);
            o.w = fmaf(fscale, rv.w, pv.w);
            ov4[j] = o;
        }
    }
}

extern "C" void kernel_launch(void* const* d_in, const int* in_sizes, int n_in,
                              void* d_out, int out_size) {
    const float* r     = (const float*)d_in[0];   // [B,128]
    const float* s     = (const float*)d_in[1];   // [B,1]
    const float* pivot = (const float*)d_in[2];   // [128]
    const float* W1    = (const float*)d_in[3];   // [128,256]
    const float* b1    = (const float*)d_in[4];   // [256]
    const float* w2    = (const float*)d_in[5];   // [256]
    const float* b2    = (const float*)d_in[6];   // [1]
    const int* n_iter  = (n_in > 7) ? (const int*)d_in[7] : nullptr;
    float* out = (float*)d_out;

    const int B = in_sizes[0] / D_DIM;

    prep_kernel<<<8, H_DIM>>>(pivot, W1, b1, w2);

    const int rows_per_block = (256 / 32) * ROWS;  // 32 rows/block
    const int blocks = (B + rows_per_block - 1) / rows_per_block;
    raymarch_kernel<<<blocks, 256>>>(r, s, pivot, w2, b2, n_iter, out, B);
}